// round 17
// baseline (speedup 1.0000x reference)
#include <cuda_runtime.h>
#include <math.h>

#define FRAME_SIZE 160
#define LPC_N 16
#define T_LEN 2400
#define T4 (T_LEN / 4)               // 600 float4 groups per row
#define N_FRAMES 15
#define B_SZ 1024

#define OG 60                        // output groups per warp (240 samples)
#define WARPS_PER_ROW (T4 / OG)      // 10
#define WPB 4
#define NTHREADS (WPB * 32)
#define NBLOCKS (B_SZ * WARPS_PER_ROW / WPB)   // 2560

#define SCALE    (255.0f / 32768.0f)
#define SCALE_1  (32768.0f / 255.0f)

__device__ __forceinline__ float ex2_approx(float x) {
    float y; asm("ex2.approx.f32 %0, %1;" : "=f"(y) : "f"(x)); return y;
}
__device__ __forceinline__ float lg2_approx(float x) {
    float y; asm("lg2.approx.f32 %0, %1;" : "=f"(y) : "f"(x)); return y;
}

// mu-law decode, folded: w = v/16 - 8 => linear = copysign(SCALE_1*(2^|w|-1), w)
// u2l(128) == +0 exactly (history pad).
__device__ __forceinline__ float u2l(float v) {
    float w = fmaf(v, 0.0625f, -8.0f);
    float m = fmaf(SCALE_1, ex2_approx(fabsf(w)), -SCALE_1);
    return copysignf(m, w);
}
// l2u(-a) = clip(128 - copysign(16*log2(1 + SCALE*|a|), a), 0, 255)
__device__ __forceinline__ float l2u_neg(float a) {
    float u = lg2_approx(fmaf(SCALE, fabsf(a), 1.0f));
    float s = copysignf(16.0f, a);
    return fminf(fmaxf(fmaf(-s, u, 128.0f), 0.0f), 255.0f);
}

__device__ __forceinline__ float4 dec4(float4 v) {
    float4 d;
    d.x = u2l(v.x); d.y = u2l(v.y); d.z = u2l(v.z); d.w = u2l(v.w);
    return d;
}

// R16 champion + own-decode register bypass:
//   warp w: row b = w/10, segment r = w%10. Owns output groups [60r, 60r+60).
//   Every lane decodes exactly 2 consecutive groups (64 = 60 output + 4 halo)
//   in ONE uniform pass. Lane l's own decodes ARE window slots 2l, 2l+1 of its
//   own FIR window -> kept in registers; only 3 LDS.128 (pass A) + 1 (pass B).
//   __syncwarp only; sequential two-pass FIR keeps the live set small.
__global__ __launch_bounds__(NTHREADS)
void diff_pred_kernel(const float4* __restrict__ sig,
                      const float*  __restrict__ lpc,
                      float4* __restrict__ out) {
    __shared__ __align__(16) float4 strip[WPB][OG + 4];   // 64 slots per warp

    const int wid = threadIdx.x >> 5;
    const int l   = threadIdx.x & 31;
    const int w   = blockIdx.x * WPB + wid;
    const int b   = w / WARPS_PER_ROW;
    const int r   = w - b * WARPS_PER_ROW;
    const int gb  = OG * r;                   // row-local output group base
    const int q0  = gb - 4 + 2 * l;           // this lane's first decode group

    const float4* srow = sig + (size_t)b * T4;

    // ---- front-batch all global loads ----
    const float4 pad = make_float4(128.f, 128.f, 128.f, 128.f);  // decodes to 0
    float4 v0 = (q0 >= 0)     ? srow[q0]     : pad;
    float4 v1 = (q0 + 1 >= 0) ? srow[q0 + 1] : pad;

    // coefficients for this lane's output pair (one frame: og even, boundary
    // at multiples of 40, so og and og+1 never straddle)
    float4 c0, c1, c2, c3;
    if (l < OG / 2) {
        const int f = (gb + 2 * l) / (FRAME_SIZE / 4);   // og / 40
        const float4* lrow = (const float4*)(lpc + (size_t)b * (N_FRAMES * LPC_N)
                                             + f * LPC_N);
        c0 = lrow[0]; c1 = lrow[1]; c2 = lrow[2]; c3 = lrow[3];
    }

    // ---- single uniform decode pass (2 groups per lane) ----
    float4 d0 = dec4(v0);
    float4 d1 = dec4(v1);
    strip[wid][2 * l]     = d0;
    strip[wid][2 * l + 1] = d1;
    __syncwarp();

    if (l >= OG / 2) return;

    const float c[LPC_N] = { c0.x, c0.y, c0.z, c0.w, c1.x, c1.y, c1.z, c1.w,
                             c2.x, c2.y, c2.z, c2.w, c3.x, c3.y, c3.z, c3.w };

    float4* orow = out + (size_t)b * T4;
    const int og = gb + 2 * l;

    // ---- pass A window: x[0..7] = OWN d0,d1 (regs); x[8..19] = 3 LDS.128 ----
    float x[20];
    x[0] = d0.x; x[1] = d0.y; x[2]  = d0.z; x[3]  = d0.w;
    x[4] = d1.x; x[5] = d1.y; x[6]  = d1.z; x[7]  = d1.w;
#pragma unroll
    for (int k = 0; k < 3; ++k) {
        float4 xx = strip[wid][2 * l + 2 + k];
        x[8 + 4 * k] = xx.x; x[9 + 4 * k] = xx.y;
        x[10 + 4 * k] = xx.z; x[11 + 4 * k] = xx.w;
    }
    {
        float a0 = 0.f, a1 = 0.f, a2 = 0.f, a3 = 0.f;
#pragma unroll
        for (int i = 0; i < LPC_N; ++i) {
            a0 = fmaf(c[i], x[16 - i], a0);
            a1 = fmaf(c[i], x[17 - i], a1);
            a2 = fmaf(c[i], x[18 - i], a2);
            a3 = fmaf(c[i], x[19 - i], a3);
        }
        float4 rA;
        rA.x = l2u_neg(a0); rA.y = l2u_neg(a1); rA.z = l2u_neg(a2); rA.w = l2u_neg(a3);
        orow[og] = rA;
    }

    // ---- pass B: slide window by one group (register shift + 1 LDS.128) ----
#pragma unroll
    for (int i = 0; i < 16; ++i) x[i] = x[i + 4];
    {
        float4 xx = strip[wid][2 * l + 5];
        x[16] = xx.x; x[17] = xx.y; x[18] = xx.z; x[19] = xx.w;

        float a0 = 0.f, a1 = 0.f, a2 = 0.f, a3 = 0.f;
#pragma unroll
        for (int i = 0; i < LPC_N; ++i) {
            a0 = fmaf(c[i], x[16 - i], a0);
            a1 = fmaf(c[i], x[17 - i], a1);
            a2 = fmaf(c[i], x[18 - i], a2);
            a3 = fmaf(c[i], x[19 - i], a3);
        }
        float4 rB;
        rB.x = l2u_neg(a0); rB.y = l2u_neg(a1); rB.z = l2u_neg(a2); rB.w = l2u_neg(a3);
        orow[og + 1] = rB;
    }
}

extern "C" void kernel_launch(void* const* d_in, const int* in_sizes, int n_in,
                              void* d_out, int out_size) {
    const float4* sig = (const float4*)d_in[0];  // (B, 2400, 1) f32
    const float*  lpc = (const float*)d_in[1];   // (B, 15, 16) f32
    float4* out = (float4*)d_out;                // (B, 2400, 1) f32

    diff_pred_kernel<<<NBLOCKS, NTHREADS>>>(sig, lpc, out);
}